// round 15
// baseline (speedup 1.0000x reference)
#include <cuda_runtime.h>
#include <cuda_bf16.h>
#include <cstdint>

#define B_   64
#define T_   4096
#define IN_  32
#define H_   128
#define G_   384
#define OUT_ 32
#define BT_  (B_ * T_)
#define GDEPTH 8          // cp.async gi ring depth
#define NWRK 24           // worker CTAs (grid 152 = GB300 SM count)
#define CHUNK 32          // pipeline chunk (steps)
#define LOOKA 2           // gi0 production lookahead (chunks)

// worker SMEM geometry
#define APAD 132          // staged row stride (floats)
#define POOLF (64 * APAD) // 8448 floats = 33.8 KB; >= scan pool (7712)

// ---------------- scratch (static __device__; allocation-free rule) ----------
__device__ float g_gi [(size_t)BT_ * G_];    // layer-0 gate pre-activations
__device__ float g_gi1[(size_t)BT_ * G_];    // layer-1 gate pre-activations
__device__ float g_y0 [(size_t)BT_ * H_];    // layer-0 outputs
__device__ unsigned g_flagx[B_];             // gi0 rows ready per batch
__device__ unsigned g_flag0[B_];             // y0 rows ready per batch
__device__ unsigned g_flag1[B_];             // gi1 rows ready per batch

typedef unsigned long long u64t;

// ---------------- packed f32x2 helpers (sm_103a FFMA2 via PTX) ---------------
__device__ __forceinline__ u64t pk2(float a, float b) {
    u64t r; asm("mov.b64 %0, {%1,%2};" : "=l"(r) : "f"(a), "f"(b)); return r;
}
__device__ __forceinline__ u64t fma2(u64t a, u64t b, u64t c) {
    u64t d; asm("fma.rn.f32x2 %0, %1, %2, %3;" : "=l"(d) : "l"(a), "l"(b), "l"(c)); return d;
}
__device__ __forceinline__ u64t add2(u64t a, u64t b) {
    u64t d; asm("add.rn.f32x2 %0, %1, %2;" : "=l"(d) : "l"(a), "l"(b)); return d;
}
__device__ __forceinline__ float2 upk2(u64t a) {
    float2 f; asm("mov.b64 {%0,%1}, %2;" : "=f"(f.x), "=f"(f.y) : "l"(a)); return f;
}

__device__ __forceinline__ float sigmf(float x) {
    return __fdividef(1.f, 1.f + __expf(-x));
}
__device__ __forceinline__ float tanhfast(float x) {
    float e = __expf(-2.f * x);
    return __fdividef(1.f - e, 1.f + e);
}

__device__ __forceinline__ uint32_t smem_u32(const void* p) {
    uint32_t a;
    asm("{ .reg .u64 t; cvta.to.shared.u64 t, %1; cvt.u32.u64 %0, t; }"
        : "=r"(a) : "l"(p));
    return a;
}
__device__ __forceinline__ void cp_async4(uint32_t saddr, const float* gaddr) {
    asm volatile("cp.async.ca.shared.global [%0], [%1], 4;" :: "r"(saddr), "l"(gaddr));
}
__device__ __forceinline__ void cp_async16(uint32_t saddr, const float* gaddr) {
    asm volatile("cp.async.ca.shared.global [%0], [%1], 16;" :: "r"(saddr), "l"(gaddr));
}
__device__ __forceinline__ void cp_commit() { asm volatile("cp.async.commit_group;"); }
__device__ __forceinline__ void cp_wait7()  { asm volatile("cp.async.wait_group 7;"); }
__device__ __forceinline__ void cp_wait0()  { asm volatile("cp.async.wait_group 0;"); }

__device__ __forceinline__ unsigned ld_acq(const unsigned* p) {
    unsigned v;
    asm volatile("ld.acquire.gpu.global.u32 %0, [%1];" : "=r"(v) : "l"(p) : "memory");
    return v;
}
__device__ __forceinline__ void st_rel(unsigned* p, unsigned v) {
    asm volatile("st.release.gpu.global.u32 [%0], %1;" :: "l"(p), "r"(v) : "memory");
}
__device__ __forceinline__ void npause() {
    asm volatile("nanosleep.u32 200;");
}

// ============================================================================
// K0: reset pipeline flags (runs before k_fused each replay; ~2us)
// ============================================================================
__global__ void k0_reset() {
    const int t = threadIdx.x;
    if (t < B_)           g_flagx[t] = 0;
    else if (t < 2 * B_)  g_flag0[t - B_] = 0;
    else if (t < 3 * B_)  g_flag1[t - 2 * B_] = 0;
}

// ============================================================================
// Worker sub-phases
// ============================================================================

// gi0 chunk: gi0[b, c*CHUNK ..) = x-chunk @ W_ih0^T + b_ih0
__device__ __forceinline__ void produce_gi0(
    int b, int c, const float* __restrict__ x,
    const float* __restrict__ Wih0, const float* __restrict__ bih0,
    float* __restrict__ sA, uint32_t sA_u32)
{
    const int tid = threadIdx.x;
    const size_t row0 = (size_t)b * T_ + (size_t)c * CHUNK;

    __syncthreads();                       // prior sA readers done
    // stage x chunk: CHUNK x 32 floats (1024 f = 256 float4)
    if (tid < 256) {
        const int m = tid >> 3, c4 = (tid & 7) * 4;
        cp_async16(sA_u32 + (uint32_t)(m * IN_ + c4) * 4,
                   x + (row0 + m) * IN_ + c4);
    }
    cp_commit(); cp_wait0();

    // weight row (32 floats) + bias from L2
    u64t w0[16];
    {
        const float4* wr = (const float4*)(Wih0 + (size_t)tid * IN_);
#pragma unroll
        for (int q = 0; q < 8; q++) {
            float4 w4 = __ldg(wr + q);
            w0[2 * q]     = pk2(w4.x, w4.y);
            w0[2 * q + 1] = pk2(w4.z, w4.w);
        }
    }
    const float bias = __ldg(bih0 + tid);
    __syncthreads();

    float* dst = g_gi + row0 * G_ + tid;
#pragma unroll 1
    for (int m = 0; m < CHUNK; m++) {
        const ulonglong2* xr = (const ulonglong2*)(sA + m * IN_);
        u64t a0 = 0ull, a1 = 0ull;
#pragma unroll
        for (int q = 0; q < 8; q++) {
            ulonglong2 xp = xr[q];
            a0 = fma2(w0[2 * q],     xp.x, a0);
            a1 = fma2(w0[2 * q + 1], xp.y, a1);
        }
        float2 s = upk2(add2(a0, a1));
        dst[(size_t)m * G_] = s.x + s.y + bias;
    }

    __threadfence();
    __syncthreads();
    if (tid == 0) st_rel(&g_flagx[b], (unsigned)((c + 1) * CHUNK));
}

// gi1 chunk: gi1[b, c*CHUNK ..) = y0-chunk @ W_ih1^T + b_ih1
__device__ __forceinline__ void produce_gi1(
    int b, int c,
    const float* __restrict__ Wih1, const float* __restrict__ bih1,
    float* __restrict__ sA, uint32_t sA_u32)
{
    const int tid = threadIdx.x;
    const size_t row0 = (size_t)b * T_ + (size_t)c * CHUNK;

    __syncthreads();                       // prior sA readers done
    // stage y0 chunk: CHUNK x 128 floats (4096 f = 1024 float4)
    for (int idx = tid; idx < CHUNK * 32; idx += 384) {
        const int m = idx >> 5, c4 = (idx & 31) * 4;
        cp_async16(sA_u32 + (uint32_t)(m * APAD + c4) * 4,
                   g_y0 + (row0 + m) * H_ + c4);
    }
    cp_commit(); cp_wait0();

    // weight row (128 floats) + bias from L2
    u64t wp[64];
    {
        const float4* wr = (const float4*)(Wih1 + (size_t)tid * H_);
#pragma unroll
        for (int q = 0; q < 16; q++) {
            float4 wA = __ldg(wr + 2 * q);
            float4 wB = __ldg(wr + 2 * q + 1);
            wp[4 * q + 0] = pk2(wA.x, wA.y);
            wp[4 * q + 1] = pk2(wA.z, wA.w);
            wp[4 * q + 2] = pk2(wB.x, wB.y);
            wp[4 * q + 3] = pk2(wB.z, wB.w);
        }
    }
    const float bias = __ldg(bih1 + tid);
    __syncthreads();

    float* dst = g_gi1 + row0 * G_ + tid;
#pragma unroll 1
    for (int m = 0; m < CHUNK; m++) {
        const ulonglong2* h2 = (const ulonglong2*)(sA + m * APAD);
        u64t a0 = 0ull, a1 = 0ull, a2 = 0ull, a3 = 0ull;
#pragma unroll
        for (int q = 0; q < 16; q++) {
            ulonglong2 p0 = h2[2 * q];
            ulonglong2 p1 = h2[2 * q + 1];
            a0 = fma2(wp[4 * q + 0], p0.x, a0);
            a1 = fma2(wp[4 * q + 1], p0.y, a1);
            a2 = fma2(wp[4 * q + 2], p1.x, a2);
            a3 = fma2(wp[4 * q + 3], p1.y, a3);
        }
        float2 sf = upk2(add2(add2(a0, a1), add2(a2, a3)));
        dst[(size_t)m * G_] = sf.x + sf.y + bias;
    }

    __threadfence();
    __syncthreads();
    if (tid == 0) st_rel(&g_flag1[b], (unsigned)((c + 1) * CHUNK));
}

// ============================================================================
// Worker role: produce gi0 (LOOKA chunks ahead) then gi1 (gated on y0 flags).
// Deadlock-free: gi0 for chunk c+LOOKA is produced BEFORE waiting on flag0
// for chunk c, and L0 only needs gi0 up to ~step 32c+41 to reach the step
// (32c+32) that satisfies the worker's flag0 wait.
// ============================================================================
__device__ __forceinline__ void worker_role(
    int w, const float* __restrict__ x,
    const float* __restrict__ Wih0, const float* __restrict__ bih0,
    const float* __restrict__ Wih1, const float* __restrict__ bih1,
    float* __restrict__ pool)
{
    float* sA = pool;
    const int tid = threadIdx.x;
    const uint32_t sA_u32 = smem_u32(sA);

    int bs[3]; int nb = 0;
    for (int i = 0; i < 3; i++) {
        int bb = w + i * NWRK;
        if (bb < B_) bs[nb++] = bb;
    }

    const int NCH = T_ / CHUNK;

    // prologue: gi0 lookahead
    for (int la = 0; la < LOOKA; la++)
        for (int i = 0; i < nb; i++)
            produce_gi0(bs[i], la, x, Wih0, bih0, sA, sA_u32);

    for (int c = 0; c < NCH; c++) {
        const int cg = c + LOOKA;
        if (cg < NCH)
            for (int i = 0; i < nb; i++)
                produce_gi0(bs[i], cg, x, Wih0, bih0, sA, sA_u32);

        const unsigned need = (unsigned)((c + 1) * CHUNK);
        for (int i = 0; i < nb; i++) {
            const int b = bs[i];
            if (tid == 0) {
                while (ld_acq(&g_flag0[b]) < need) npause();
            }
            produce_gi1(b, c, Wih1, bih1, sA, sA_u32);
        }
    }
}

// ============================================================================
// Scan role (R14-proven, unchanged). 384 threads, one gate row each; W_hh in
// regs; h ping-pong in SMEM; 2 barriers/step; gi via 8-deep cp.async ring,
// gated on a producer flag; n-threads carry h in a register; y0 STG deferred.
// ============================================================================
template <int DO_FC, int STORE_Y>
__device__ __forceinline__ void scan_role(
    int b, const float* __restrict__ Whh, const float* __restrict__ bhh,
    const float* __restrict__ gi_base,
    unsigned* pub_flag, const unsigned* gate_flag,
    const float* __restrict__ fcw, const float* __restrict__ fcb,
    float* __restrict__ out, float* __restrict__ h_final,
    float* __restrict__ pool)
{
    float* sgi  = pool;                       // [GDEPTH][G_]
    float* sh0  = pool + GDEPTH * G_;         // [H_]
    float* sh1  = sh0 + H_;
    float* sh_r = sh1 + H_;
    float* sh_z = sh_r + H_;
    float* sfc  = sh_z + H_;                  // [OUT_*H_]
    float* sfcb = sfc + OUT_ * H_;            // [OUT_]

    const int r = threadIdx.x;       // gate row (r:0-127, z:128-255, n:256-383)

    u64t wp[64];
    {
        const float4* wr = (const float4*)(Whh + (size_t)r * H_);
#pragma unroll
        for (int q = 0; q < 16; q++) {
            float4 wA = __ldg(wr + 2 * q);
            float4 wB = __ldg(wr + 2 * q + 1);
            wp[4 * q + 0] = pk2(wA.x, wA.y);
            wp[4 * q + 1] = pk2(wA.z, wA.w);
            wp[4 * q + 2] = pk2(wB.x, wB.y);
            wp[4 * q + 3] = pk2(wB.z, wB.w);
        }
    }
    const float bias = __ldg(bhh + r);
    if (r < H_) sh0[r] = 0.f;
    if (DO_FC) {
        for (int i = r; i < OUT_ * H_; i += 384) sfc[i] = fcw[i];
        if (r < OUT_) sfcb[r] = fcb[r];
    }

    // ---- gi ring prologue -------------------------------------------------
    const float* gip = gi_base + (size_t)b * T_ * G_ + r;
    const uint32_t sgi_base = smem_u32(sgi + r);
    unsigned known = 0;
    if (gate_flag) {
        do { known = ld_acq(gate_flag); if (known < GDEPTH) npause(); }
        while (known < GDEPTH);
    }
#pragma unroll
    for (int d = 0; d < GDEPTH; d++) {
        cp_async4(sgi_base + (uint32_t)d * (G_ * 4), gip + (size_t)d * G_);
        cp_commit();
    }
    __syncthreads();

    float* hcur = sh0;
    float* hnxt = sh1;
    float* ybase = g_y0 + (size_t)b * T_ * H_ + (r - 256);     // n-threads only
    float* obase = out + (size_t)b * T_ * OUT_;

    const int o   = r >> 3;          // FC output index (r/z threads)
    const int seg = r & 7;
    const float* fcrow = sfc + o * H_ + seg * 16;

    float h_my = 0.f;                // n-thread's own h element (register)
    float y_pend = 0.f;              // deferred y0 store value

    for (int t = 0; t < T_; t++) {
        const int slot = t & (GDEPTH - 1);

        cp_wait7();                                            // stage t landed
        const float gi_cur = sgi[slot * G_ + r];

        // deferred y0 store for step t-1 (issues under the matvec)
        if (STORE_Y && r >= 256 && t > 0)
            ybase[(size_t)(t - 1) * H_] = y_pend;

        // refill slot for step t+GDEPTH (gated on producer)
        const int tp = (t + GDEPTH < T_) ? t + GDEPTH : T_ - 1;
        if (gate_flag && known < (unsigned)(tp + 1)) {
            do { known = ld_acq(gate_flag); if (known < (unsigned)(tp + 1)) npause(); }
            while (known < (unsigned)(tp + 1));
        }
        cp_async4(sgi_base + (uint32_t)slot * (G_ * 4), gip + (size_t)tp * G_);
        cp_commit();

        // ---- phase 1: gh = W_hh[r,:] . h + b ; r,z publish sigmoids --------
        u64t a0 = 0ull, a1 = 0ull, a2 = 0ull, a3 = 0ull;
        const ulonglong2* h2 = (const ulonglong2*)hcur;
#pragma unroll
        for (int q = 0; q < 16; q++) {
            ulonglong2 p0 = h2[2 * q];
            ulonglong2 p1 = h2[2 * q + 1];
            a0 = fma2(wp[4 * q + 0], p0.x, a0);
            a1 = fma2(wp[4 * q + 1], p0.y, a1);
            a2 = fma2(wp[4 * q + 2], p1.x, a2);
            a3 = fma2(wp[4 * q + 3], p1.y, a3);
        }
        float2 sf = upk2(add2(add2(a0, a1), add2(a2, a3)));
        const float gh = sf.x + sf.y + bias;

        if (r < 128)      sh_r[r]       = sigmf(gi_cur + gh);
        else if (r < 256) sh_z[r - 128] = sigmf(gi_cur + gh);
        __syncthreads();                                        // bar 1

        // ---- phase 2: n-threads update h; r/z threads do FC for t-1 --------
        if (r >= 256) {
            const int j = r - 256;
            const float nv = tanhfast(fmaf(sh_r[j], gh, gi_cur));
            const float hnew = fmaf(sh_z[j], h_my - nv, nv);    // (1-z)*n + z*h
            h_my = hnew;
            hnxt[j] = hnew;
            y_pend = hnew;
        } else if (DO_FC && t > 0) {
            const float* hh = hcur + seg * 16;                  // h_{t-1}
            float s = 0.f;
#pragma unroll
            for (int k = 0; k < 16; k++) s = fmaf(fcrow[k], hh[k], s);
            s += __shfl_down_sync(0xffffffffu, s, 4, 8);
            s += __shfl_down_sync(0xffffffffu, s, 2, 8);
            s += __shfl_down_sync(0xffffffffu, s, 1, 8);
            if (seg == 0) obase[(size_t)(t - 1) * OUT_ + o] = s + sfcb[o];
        }

        // publish rows < t (row t-1 was stored during this step's phase 1)
        const bool pub_now = STORE_Y && ((t & 15) == 0) && (t > 0);
        if (pub_now) __threadfence();
        __syncthreads();                                        // bar 2
        if (pub_now && r == 0) st_rel(pub_flag, (unsigned)t);

        float* tmp = hcur; hcur = hnxt; hnxt = tmp;
    }

    // tail: last y0 row + final flag publish
    if (STORE_Y) {
        if (r >= 256) ybase[(size_t)(T_ - 1) * H_] = y_pend;
        __threadfence();
        __syncthreads();
        if (r == 0) st_rel(pub_flag, (unsigned)T_);
    }

    // final-step FC (h_{T-1} sits in hcur after the last swap)
    if (DO_FC && r < 256) {
        const float* hh = hcur + seg * 16;
        float s = 0.f;
#pragma unroll
        for (int k = 0; k < 16; k++) s = fmaf(fcrow[k], hh[k], s);
        s += __shfl_down_sync(0xffffffffu, s, 4, 8);
        s += __shfl_down_sync(0xffffffffu, s, 2, 8);
        s += __shfl_down_sync(0xffffffffu, s, 1, 8);
        if (seg == 0) obase[(size_t)(T_ - 1) * OUT_ + o] = s + sfcb[o];
    }
    if (r >= 256) h_final[(size_t)b * H_ + (r - 256)] = h_my;
}

// ============================================================================
// Fused persistent kernel: 152 CTAs (GB300 152 SMs; all wave-1 resident).
//   CTA 0..63    : layer-0 scan (batch = bid), gi0 ring gated on g_flagx
//   CTA 64..87   : workers: gi0 producer (lookahead) + gi1 producer
//   CTA 88..151  : layer-1 scan + FC (batch = bid-88), gated on g_flag1
// ============================================================================
__global__ void __launch_bounds__(384, 1) k_fused(
    const float* __restrict__ x,
    const float* __restrict__ Wih0, const float* __restrict__ bih0,
    const float* __restrict__ Whh0, const float* __restrict__ bhh0,
    const float* __restrict__ Wih1, const float* __restrict__ bih1,
    const float* __restrict__ Whh1, const float* __restrict__ bhh1,
    const float* __restrict__ fcw,  const float* __restrict__ fcb,
    float* __restrict__ out, float* __restrict__ hout)
{
    __shared__ __align__(16) float pool[POOLF];

    const int bid = blockIdx.x;

    if (bid < B_) {
        scan_role<0, 1>(bid, Whh0, bhh0, g_gi,
                        /*pub=*/&g_flag0[bid], /*gate=*/&g_flagx[bid],
                        fcw, fcb, out, hout, pool);
    } else if (bid < B_ + NWRK) {
        worker_role(bid - B_, x, Wih0, bih0, Wih1, bih1, pool);
    } else {
        const int b = bid - (B_ + NWRK);
        scan_role<1, 0>(b, Whh1, bhh1, g_gi1,
                        /*pub=*/nullptr, /*gate=*/&g_flag1[b],
                        fcw, fcb, out, hout + (size_t)B_ * H_, pool);
    }
}

// ============================================================================
extern "C" void kernel_launch(void* const* d_in, const int* in_sizes, int n_in,
                              void* d_out, int out_size) {
    const float* x    = (const float*)d_in[0];
    const float* Wih0 = (const float*)d_in[1];
    const float* Whh0 = (const float*)d_in[2];
    const float* bih0 = (const float*)d_in[3];
    const float* bhh0 = (const float*)d_in[4];
    const float* Wih1 = (const float*)d_in[5];
    const float* Whh1 = (const float*)d_in[6];
    const float* bih1 = (const float*)d_in[7];
    const float* bhh1 = (const float*)d_in[8];
    const float* fcw  = (const float*)d_in[9];
    const float* fcb  = (const float*)d_in[10];

    float* out  = (float*)d_out;                       // [B,T,OUT]
    float* hout = out + (size_t)B_ * T_ * OUT_;        // [2,B,H] stacked after out

    // K0: flag reset (graph-ordered before fused; replaces serial K1)
    k0_reset<<<1, 3 * B_>>>();
    // Fused pipeline: gi0 producers || L0 scan || gi1 producers || L1 scan+FC
    k_fused<<<B_ + NWRK + B_, 384>>>(x, Wih0, bih0, Whh0, bhh0,
                                     Wih1, bih1, Whh1, bhh1,
                                     fcw, fcb, out, hout);
}

// round 16
// speedup vs baseline: 1.5689x; 1.5689x over previous
#include <cuda_runtime.h>
#include <cuda_bf16.h>
#include <cstdint>

#define B_   64
#define T_   4096
#define IN_  32
#define H_   128
#define G_   384
#define OUT_ 32
#define BT_  (B_ * T_)
#define GDEPTH 8          // cp.async gi ring depth
#define NWRK 24           // gi1 worker CTAs (grid 152 = GB300 SM count)
#define CHUNK 64          // pipeline chunk (steps)
#define K1ROWS 128        // K1 rows per CTA

// worker SMEM geometry
#define APAD 132          // staged row stride (floats)
#define POOLF (64 * APAD) // 8448 floats = 33.8 KB; >= scan pool (7712)

// ---------------- scratch (static __device__; allocation-free rule) ----------
__device__ float g_gi [(size_t)BT_ * G_];    // layer-0 gate pre-activations
__device__ float g_gi1[(size_t)BT_ * G_];    // layer-1 gate pre-activations
__device__ float g_y0 [(size_t)BT_ * H_];    // layer-0 outputs
__device__ unsigned g_flag0[B_];             // y0 rows ready per batch
__device__ unsigned g_flag1[B_];             // gi1 rows ready per batch

typedef unsigned long long u64t;

// ---------------- packed f32x2 helpers (sm_103a FFMA2 via PTX) ---------------
__device__ __forceinline__ u64t pk2(float a, float b) {
    u64t r; asm("mov.b64 %0, {%1,%2};" : "=l"(r) : "f"(a), "f"(b)); return r;
}
__device__ __forceinline__ u64t fma2(u64t a, u64t b, u64t c) {
    u64t d; asm("fma.rn.f32x2 %0, %1, %2, %3;" : "=l"(d) : "l"(a), "l"(b), "l"(c)); return d;
}
__device__ __forceinline__ u64t add2(u64t a, u64t b) {
    u64t d; asm("add.rn.f32x2 %0, %1, %2;" : "=l"(d) : "l"(a), "l"(b)); return d;
}
__device__ __forceinline__ float2 upk2(u64t a) {
    float2 f; asm("mov.b64 {%0,%1}, %2;" : "=f"(f.x), "=f"(f.y) : "l"(a)); return f;
}

__device__ __forceinline__ float sigmf(float x) {
    return __fdividef(1.f, 1.f + __expf(-x));
}
__device__ __forceinline__ float tanhfast(float x) {
    float e = __expf(-2.f * x);
    return __fdividef(1.f - e, 1.f + e);
}

__device__ __forceinline__ uint32_t smem_u32(const void* p) {
    uint32_t a;
    asm("{ .reg .u64 t; cvta.to.shared.u64 t, %1; cvt.u32.u64 %0, t; }"
        : "=r"(a) : "l"(p));
    return a;
}
__device__ __forceinline__ void cp_async4(uint32_t saddr, const float* gaddr) {
    asm volatile("cp.async.ca.shared.global [%0], [%1], 4;" :: "r"(saddr), "l"(gaddr));
}
__device__ __forceinline__ void cp_async16(uint32_t saddr, const float* gaddr) {
    asm volatile("cp.async.ca.shared.global [%0], [%1], 16;" :: "r"(saddr), "l"(gaddr));
}
__device__ __forceinline__ void cp_commit() { asm volatile("cp.async.commit_group;"); }
__device__ __forceinline__ void cp_wait7()  { asm volatile("cp.async.wait_group 7;"); }
__device__ __forceinline__ void cp_wait0()  { asm volatile("cp.async.wait_group 0;"); }

__device__ __forceinline__ unsigned ld_acq(const unsigned* p) {
    unsigned v;
    asm volatile("ld.acquire.gpu.global.u32 %0, [%1];" : "=r"(v) : "l"(p) : "memory");
    return v;
}
__device__ __forceinline__ void st_rel(unsigned* p, unsigned v) {
    asm volatile("st.release.gpu.global.u32 [%0], %1;" :: "l"(p), "r"(v) : "memory");
}
__device__ __forceinline__ void npause() {
    asm volatile("nanosleep.u32 200;");
}

// ============================================================================
// K1: gi0 = x @ W_ih0^T + b_ih0 (K1ROWS rows/CTA; also resets flags)
// ============================================================================
__global__ void k1_gi0(const float* __restrict__ x,
                       const float* __restrict__ W,
                       const float* __restrict__ b) {
    __shared__ __align__(16) float sx[K1ROWS * IN_];
    const int tid = threadIdx.x;                 // gate row 0..383
    const size_t bt0 = (size_t)blockIdx.x * K1ROWS;

    if (blockIdx.x == 0 && tid < 2 * B_) {
        if (tid < B_) g_flag0[tid] = 0; else g_flag1[tid - B_] = 0;
    }

    for (int i = tid; i < K1ROWS * IN_ / 4; i += 384)
        ((float4*)sx)[i] = ((const float4*)(x + bt0 * IN_))[i];

    u64t wp[16];
    {
        const float4* wr = (const float4*)(W + (size_t)tid * IN_);
#pragma unroll
        for (int q = 0; q < 8; q++) {
            float4 w4 = __ldg(wr + q);
            wp[2 * q]     = pk2(w4.x, w4.y);
            wp[2 * q + 1] = pk2(w4.z, w4.w);
        }
    }
    const float bias = __ldg(b + tid);
    __syncthreads();

#pragma unroll 4
    for (int row = 0; row < K1ROWS; row++) {
        const ulonglong2* xr = (const ulonglong2*)(sx + row * IN_);
        u64t a0 = 0ull, a1 = 0ull;
#pragma unroll
        for (int q = 0; q < 8; q++) {
            ulonglong2 xp = xr[q];
            a0 = fma2(wp[2 * q],     xp.x, a0);
            a1 = fma2(wp[2 * q + 1], xp.y, a1);
        }
        float2 s = upk2(add2(a0, a1));
        g_gi[(bt0 + row) * G_ + tid] = s.x + s.y + bias;
    }
}

// ============================================================================
// Worker role (R14-proven): each thread owns W_ih1 row `tid` in registers;
// per 64-step chunk: stage y0 chunk once via cp.async, then 64 broadcast
// matvecs (32 LDS.128 + 64 fma2 each) with NO inner barriers.
// ============================================================================
__device__ __forceinline__ void worker_role(
    int w, const float* __restrict__ W, const float* __restrict__ bias,
    float* __restrict__ pool)
{
    float* sA = pool;                        // 64 x APAD (y0 chunk)
    const int tid = threadIdx.x;             // gate row 0..383
    const uint32_t sA_u32 = smem_u32(sA);

    u64t wp[64];
    {
        const float4* wr = (const float4*)(W + (size_t)tid * H_);
#pragma unroll
        for (int q = 0; q < 16; q++) {
            float4 wA = __ldg(wr + 2 * q);
            float4 wB = __ldg(wr + 2 * q + 1);
            wp[4 * q + 0] = pk2(wA.x, wA.y);
            wp[4 * q + 1] = pk2(wA.z, wA.w);
            wp[4 * q + 2] = pk2(wB.x, wB.y);
            wp[4 * q + 3] = pk2(wB.z, wB.w);
        }
    }
    const float bias_t = __ldg(bias + tid);

    int bs[3]; int nb = 0;
    for (int i = 0; i < 3; i++) {
        int bb = w + i * NWRK;
        if (bb < B_) bs[nb++] = bb;
    }

    for (int c = 0; c < T_ / CHUNK; c++) {
        const unsigned need = (unsigned)((c + 1) * CHUNK);
        for (int i = 0; i < nb; i++) {
            const int b = bs[i];
            if (tid == 0) {
                while (ld_acq(&g_flag0[b]) < need) npause();
            }
            __syncthreads();   // also isolates prior compute reads from restage

            const size_t arow = (size_t)b * T_ + (size_t)c * CHUNK;

            // ---- stage y0 chunk: 64 x 128 floats, coalesced cp.async ----
            for (int idx = tid; idx < 2048; idx += 384) {
                const int m = idx >> 5, c4 = idx & 31;
                cp_async16(sA_u32 + (uint32_t)(m * APAD + c4 * 4) * 4,
                           g_y0 + (arow + m) * H_ + c4 * 4);
            }
            cp_commit(); cp_wait0();
            __syncthreads();

            // ---- 64 matvecs: gi1[m][tid] = W_row . y0[m] + b ----
            float* dst = g_gi1 + arow * G_ + tid;
#pragma unroll 1
            for (int m = 0; m < CHUNK; m++) {
                const ulonglong2* h2 = (const ulonglong2*)(sA + m * APAD);
                u64t a0 = 0ull, a1 = 0ull, a2 = 0ull, a3 = 0ull;
#pragma unroll
                for (int q = 0; q < 16; q++) {
                    ulonglong2 p0 = h2[2 * q];
                    ulonglong2 p1 = h2[2 * q + 1];
                    a0 = fma2(wp[4 * q + 0], p0.x, a0);
                    a1 = fma2(wp[4 * q + 1], p0.y, a1);
                    a2 = fma2(wp[4 * q + 2], p1.x, a2);
                    a3 = fma2(wp[4 * q + 3], p1.y, a3);
                }
                float2 sf = upk2(add2(add2(a0, a1), add2(a2, a3)));
                dst[(size_t)m * G_] = sf.x + sf.y + bias_t;
            }

            __threadfence();
            __syncthreads();
            if (tid == 0) st_rel(&g_flag1[b], need);
        }
    }
}

// ============================================================================
// Scan role (R14-proven). 384 threads, one gate row each; W_hh row in regs;
// h ping-pong in SMEM; 2 barriers/step; gi via 8-deep cp.async ring.
// n-threads carry h in a register; y0 STG deferred to next step's matvec.
// ============================================================================
template <int DO_FC, int STORE_Y>
__device__ __forceinline__ void scan_role(
    int b, const float* __restrict__ Whh, const float* __restrict__ bhh,
    const float* __restrict__ gi_base,
    unsigned* pub_flag, const unsigned* gate_flag,
    const float* __restrict__ fcw, const float* __restrict__ fcb,
    float* __restrict__ out, float* __restrict__ h_final,
    float* __restrict__ pool)
{
    float* sgi  = pool;                       // [GDEPTH][G_]
    float* sh0  = pool + GDEPTH * G_;         // [H_]
    float* sh1  = sh0 + H_;
    float* sh_r = sh1 + H_;
    float* sh_z = sh_r + H_;
    float* sfc  = sh_z + H_;                  // [OUT_*H_]
    float* sfcb = sfc + OUT_ * H_;            // [OUT_]

    const int r = threadIdx.x;       // gate row (r:0-127, z:128-255, n:256-383)

    u64t wp[64];
    {
        const float4* wr = (const float4*)(Whh + (size_t)r * H_);
#pragma unroll
        for (int q = 0; q < 16; q++) {
            float4 wA = __ldg(wr + 2 * q);
            float4 wB = __ldg(wr + 2 * q + 1);
            wp[4 * q + 0] = pk2(wA.x, wA.y);
            wp[4 * q + 1] = pk2(wA.z, wA.w);
            wp[4 * q + 2] = pk2(wB.x, wB.y);
            wp[4 * q + 3] = pk2(wB.z, wB.w);
        }
    }
    const float bias = __ldg(bhh + r);
    if (r < H_) sh0[r] = 0.f;
    if (DO_FC) {
        for (int i = r; i < OUT_ * H_; i += 384) sfc[i] = fcw[i];
        if (r < OUT_) sfcb[r] = fcb[r];
    }

    // ---- gi ring prologue -------------------------------------------------
    const float* gip = gi_base + (size_t)b * T_ * G_ + r;
    const uint32_t sgi_base = smem_u32(sgi + r);
    unsigned known = 0;
    if (gate_flag) {
        do { known = ld_acq(gate_flag); if (known < GDEPTH) npause(); }
        while (known < GDEPTH);
    }
#pragma unroll
    for (int d = 0; d < GDEPTH; d++) {
        cp_async4(sgi_base + (uint32_t)d * (G_ * 4), gip + (size_t)d * G_);
        cp_commit();
    }
    __syncthreads();

    float* hcur = sh0;
    float* hnxt = sh1;
    float* ybase = g_y0 + (size_t)b * T_ * H_ + (r - 256);     // n-threads only
    float* obase = out + (size_t)b * T_ * OUT_;

    const int o   = r >> 3;          // FC output index (r/z threads)
    const int seg = r & 7;
    const float* fcrow = sfc + o * H_ + seg * 16;

    float h_my = 0.f;                // n-thread's own h element (register)
    float y_pend = 0.f;              // deferred y0 store value

    for (int t = 0; t < T_; t++) {
        const int slot = t & (GDEPTH - 1);

        cp_wait7();                                            // stage t landed
        const float gi_cur = sgi[slot * G_ + r];

        // deferred y0 store for step t-1 (issues under the matvec)
        if (STORE_Y && r >= 256 && t > 0)
            ybase[(size_t)(t - 1) * H_] = y_pend;

        // refill slot for step t+GDEPTH (gated on producer if needed)
        const int tp = (t + GDEPTH < T_) ? t + GDEPTH : T_ - 1;
        if (gate_flag && known < (unsigned)(tp + 1)) {
            do { known = ld_acq(gate_flag); if (known < (unsigned)(tp + 1)) npause(); }
            while (known < (unsigned)(tp + 1));
        }
        cp_async4(sgi_base + (uint32_t)slot * (G_ * 4), gip + (size_t)tp * G_);
        cp_commit();

        // ---- phase 1: gh = W_hh[r,:] . h + b ; r,z publish sigmoids --------
        u64t a0 = 0ull, a1 = 0ull, a2 = 0ull, a3 = 0ull;
        const ulonglong2* h2 = (const ulonglong2*)hcur;
#pragma unroll
        for (int q = 0; q < 16; q++) {
            ulonglong2 p0 = h2[2 * q];
            ulonglong2 p1 = h2[2 * q + 1];
            a0 = fma2(wp[4 * q + 0], p0.x, a0);
            a1 = fma2(wp[4 * q + 1], p0.y, a1);
            a2 = fma2(wp[4 * q + 2], p1.x, a2);
            a3 = fma2(wp[4 * q + 3], p1.y, a3);
        }
        float2 sf = upk2(add2(add2(a0, a1), add2(a2, a3)));
        const float gh = sf.x + sf.y + bias;

        if (r < 128)      sh_r[r]       = sigmf(gi_cur + gh);
        else if (r < 256) sh_z[r - 128] = sigmf(gi_cur + gh);
        __syncthreads();                                        // bar 1

        // ---- phase 2: n-threads update h; r/z threads do FC for t-1 --------
        if (r >= 256) {
            const int j = r - 256;
            const float nv = tanhfast(fmaf(sh_r[j], gh, gi_cur));
            const float hnew = fmaf(sh_z[j], h_my - nv, nv);    // (1-z)*n + z*h
            h_my = hnew;
            hnxt[j] = hnew;
            y_pend = hnew;
        } else if (DO_FC && t > 0) {
            const float* hh = hcur + seg * 16;                  // h_{t-1}
            float s = 0.f;
#pragma unroll
            for (int k = 0; k < 16; k++) s = fmaf(fcrow[k], hh[k], s);
            s += __shfl_down_sync(0xffffffffu, s, 4, 8);
            s += __shfl_down_sync(0xffffffffu, s, 2, 8);
            s += __shfl_down_sync(0xffffffffu, s, 1, 8);
            if (seg == 0) obase[(size_t)(t - 1) * OUT_ + o] = s + sfcb[o];
        }

        // publish rows < t (row t-1 was stored during this step's phase 1)
        const bool pub_now = STORE_Y && ((t & 15) == 0) && (t > 0);
        if (pub_now) __threadfence();
        __syncthreads();                                        // bar 2
        if (pub_now && r == 0) st_rel(pub_flag, (unsigned)t);

        float* tmp = hcur; hcur = hnxt; hnxt = tmp;
    }

    // tail: last y0 row + final flag publish
    if (STORE_Y) {
        if (r >= 256) ybase[(size_t)(T_ - 1) * H_] = y_pend;
        __threadfence();
        __syncthreads();
        if (r == 0) st_rel(pub_flag, (unsigned)T_);
    }

    // final-step FC (h_{T-1} sits in hcur after the last swap)
    if (DO_FC && r < 256) {
        const float* hh = hcur + seg * 16;
        float s = 0.f;
#pragma unroll
        for (int k = 0; k < 16; k++) s = fmaf(fcrow[k], hh[k], s);
        s += __shfl_down_sync(0xffffffffu, s, 4, 8);
        s += __shfl_down_sync(0xffffffffu, s, 2, 8);
        s += __shfl_down_sync(0xffffffffu, s, 1, 8);
        if (seg == 0) obase[(size_t)(T_ - 1) * OUT_ + o] = s + sfcb[o];
    }
    if (r >= 256) h_final[(size_t)b * H_ + (r - 256)] = h_my;
}

// ============================================================================
// Fused persistent kernel: 152 CTAs (GB300 has 152 SMs; all wave-1 resident).
//   CTA 0..63    : layer-0 scan (batch = bid)
//   CTA 64..87   : gi1 workers (batches w, w+24 [, w+48])
//   CTA 88..151  : layer-1 scan + FC (batch = bid-88)
// ============================================================================
__global__ void __launch_bounds__(384, 1) k_fused(
    const float* __restrict__ Whh0, const float* __restrict__ bhh0,
    const float* __restrict__ Whh1, const float* __restrict__ bhh1,
    const float* __restrict__ Wih1, const float* __restrict__ bih1,
    const float* __restrict__ fcw,  const float* __restrict__ fcb,
    float* __restrict__ out, float* __restrict__ hout)
{
    __shared__ __align__(16) float pool[POOLF];

    const int bid = blockIdx.x;

    if (bid < B_) {
        scan_role<0, 1>(bid, Whh0, bhh0, g_gi,
                        /*pub=*/&g_flag0[bid], /*gate=*/nullptr,
                        fcw, fcb, out, hout, pool);
    } else if (bid < B_ + NWRK) {
        worker_role(bid - B_, Wih1, bih1, pool);
    } else {
        const int b = bid - (B_ + NWRK);
        scan_role<1, 0>(b, Whh1, bhh1, g_gi1,
                        /*pub=*/nullptr, /*gate=*/&g_flag1[b],
                        fcw, fcb, out, hout + (size_t)B_ * H_, pool);
    }
}

// ============================================================================
extern "C" void kernel_launch(void* const* d_in, const int* in_sizes, int n_in,
                              void* d_out, int out_size) {
    const float* x    = (const float*)d_in[0];
    const float* Wih0 = (const float*)d_in[1];
    const float* Whh0 = (const float*)d_in[2];
    const float* bih0 = (const float*)d_in[3];
    const float* bhh0 = (const float*)d_in[4];
    const float* Wih1 = (const float*)d_in[5];
    const float* Whh1 = (const float*)d_in[6];
    const float* bih1 = (const float*)d_in[7];
    const float* bhh1 = (const float*)d_in[8];
    const float* fcw  = (const float*)d_in[9];
    const float* fcb  = (const float*)d_in[10];

    float* out  = (float*)d_out;                       // [B,T,OUT]
    float* hout = out + (size_t)B_ * T_ * OUT_;        // [2,B,H] stacked after out

    // K1: layer-0 input projection + flag reset (graph-ordered before fused)
    k1_gi0<<<BT_ / K1ROWS, 384>>>(x, Wih0, bih0);
    // Fused pipeline: L0 scan || gi1 workers || L1 scan+FC
    k_fused<<<B_ + NWRK + B_, 384>>>(Whh0, bhh0, Whh1, bhh1, Wih1, bih1,
                                     fcw, fcb, out, hout);
}

// round 17
// speedup vs baseline: 1.5941x; 1.0160x over previous
#include <cuda_runtime.h>
#include <cuda_bf16.h>
#include <cstdint>

#define B_   64
#define T_   4096
#define IN_  32
#define H_   128
#define G_   384
#define OUT_ 32
#define BT_  (B_ * T_)
#define GDEPTH 8          // cp.async gi ring depth (per batch)
#define NSC  32           // scan CTAs per layer (2 batches each)
#define NWRK 32           // gi1 worker CTAs (2 batches each)
#define NFC  24           // FC head CTAs
#define CHUNK 64          // pipeline chunk (steps)
#define K1ROWS 128        // K1 rows per CTA

// SMEM pool (floats): max(worker 64*132=8448, scan2 7168, fc 8384)
#define APAD 132
#define FCPAD 130
#define POOLF 8448

// ---------------- scratch (static __device__; allocation-free rule) ----------
__device__ float g_gi [(size_t)BT_ * G_];    // layer-0 gate pre-activations
__device__ float g_gi1[(size_t)BT_ * G_];    // layer-1 gate pre-activations
__device__ float g_y0 [(size_t)BT_ * H_];    // layer-0 outputs
__device__ float g_y1 [(size_t)BT_ * H_];    // layer-1 outputs
__device__ unsigned g_flag0[B_];             // y0 rows ready per batch
__device__ unsigned g_flag1[B_];             // gi1 rows ready per batch
__device__ unsigned g_flag2[B_];             // y1 rows ready per batch

typedef unsigned long long u64t;

// ---------------- packed f32x2 helpers (sm_103a FFMA2 via PTX) ---------------
__device__ __forceinline__ u64t pk2(float a, float b) {
    u64t r; asm("mov.b64 %0, {%1,%2};" : "=l"(r) : "f"(a), "f"(b)); return r;
}
__device__ __forceinline__ u64t fma2(u64t a, u64t b, u64t c) {
    u64t d; asm("fma.rn.f32x2 %0, %1, %2, %3;" : "=l"(d) : "l"(a), "l"(b), "l"(c)); return d;
}
__device__ __forceinline__ u64t add2(u64t a, u64t b) {
    u64t d; asm("add.rn.f32x2 %0, %1, %2;" : "=l"(d) : "l"(a), "l"(b)); return d;
}
__device__ __forceinline__ float2 upk2(u64t a) {
    float2 f; asm("mov.b64 {%0,%1}, %2;" : "=f"(f.x), "=f"(f.y) : "l"(a)); return f;
}

__device__ __forceinline__ float sigmf(float x) {
    return __fdividef(1.f, 1.f + __expf(-x));
}
__device__ __forceinline__ float tanhfast(float x) {
    float e = __expf(-2.f * x);
    return __fdividef(1.f - e, 1.f + e);
}

__device__ __forceinline__ uint32_t smem_u32(const void* p) {
    uint32_t a;
    asm("{ .reg .u64 t; cvta.to.shared.u64 t, %1; cvt.u32.u64 %0, t; }"
        : "=r"(a) : "l"(p));
    return a;
}
__device__ __forceinline__ void cp_async4(uint32_t saddr, const float* gaddr) {
    asm volatile("cp.async.ca.shared.global [%0], [%1], 4;" :: "r"(saddr), "l"(gaddr));
}
__device__ __forceinline__ void cp_async16(uint32_t saddr, const float* gaddr) {
    asm volatile("cp.async.ca.shared.global [%0], [%1], 16;" :: "r"(saddr), "l"(gaddr));
}
__device__ __forceinline__ void cp_commit() { asm volatile("cp.async.commit_group;"); }
__device__ __forceinline__ void cp_wait7()  { asm volatile("cp.async.wait_group 7;"); }
__device__ __forceinline__ void cp_wait0()  { asm volatile("cp.async.wait_group 0;"); }

__device__ __forceinline__ unsigned ld_acq(const unsigned* p) {
    unsigned v;
    asm volatile("ld.acquire.gpu.global.u32 %0, [%1];" : "=r"(v) : "l"(p) : "memory");
    return v;
}
__device__ __forceinline__ void st_rel(unsigned* p, unsigned v) {
    asm volatile("st.release.gpu.global.u32 [%0], %1;" :: "l"(p), "r"(v) : "memory");
}
__device__ __forceinline__ void npause() {
    asm volatile("nanosleep.u32 200;");
}

// ============================================================================
// K1: gi0 = x @ W_ih0^T + b_ih0 (K1ROWS rows/CTA; also resets flags)
// ============================================================================
__global__ void k1_gi0(const float* __restrict__ x,
                       const float* __restrict__ W,
                       const float* __restrict__ b) {
    __shared__ __align__(16) float sx[K1ROWS * IN_];
    const int tid = threadIdx.x;                 // gate row 0..383
    const size_t bt0 = (size_t)blockIdx.x * K1ROWS;

    if (blockIdx.x == 0 && tid < 3 * B_) {
        if (tid < B_)           g_flag0[tid] = 0;
        else if (tid < 2 * B_)  g_flag1[tid - B_] = 0;
        else                    g_flag2[tid - 2 * B_] = 0;
    }

    for (int i = tid; i < K1ROWS * IN_ / 4; i += 384)
        ((float4*)sx)[i] = ((const float4*)(x + bt0 * IN_))[i];

    u64t wp[16];
    {
        const float4* wr = (const float4*)(W + (size_t)tid * IN_);
#pragma unroll
        for (int q = 0; q < 8; q++) {
            float4 w4 = __ldg(wr + q);
            wp[2 * q]     = pk2(w4.x, w4.y);
            wp[2 * q + 1] = pk2(w4.z, w4.w);
        }
    }
    const float bias = __ldg(b + tid);
    __syncthreads();

#pragma unroll 4
    for (int row = 0; row < K1ROWS; row++) {
        const ulonglong2* xr = (const ulonglong2*)(sx + row * IN_);
        u64t a0 = 0ull, a1 = 0ull;
#pragma unroll
        for (int q = 0; q < 8; q++) {
            ulonglong2 xp = xr[q];
            a0 = fma2(wp[2 * q],     xp.x, a0);
            a1 = fma2(wp[2 * q + 1], xp.y, a1);
        }
        float2 s = upk2(add2(a0, a1));
        g_gi[(bt0 + row) * G_ + tid] = s.x + s.y + bias;
    }
}

// ============================================================================
// Worker role (R16-proven): gi1[b, chunk] = y0-chunk @ W_ih1^T + b.
// W row register-resident; stage chunk once; 64 broadcast matvecs.
// ============================================================================
__device__ __forceinline__ void worker_role(
    int w, const float* __restrict__ W, const float* __restrict__ bias,
    float* __restrict__ pool)
{
    float* sA = pool;                        // 64 x APAD
    const int tid = threadIdx.x;
    const uint32_t sA_u32 = smem_u32(sA);

    u64t wp[64];
    {
        const float4* wr = (const float4*)(W + (size_t)tid * H_);
#pragma unroll
        for (int q = 0; q < 16; q++) {
            float4 wA = __ldg(wr + 2 * q);
            float4 wB = __ldg(wr + 2 * q + 1);
            wp[4 * q + 0] = pk2(wA.x, wA.y);
            wp[4 * q + 1] = pk2(wA.z, wA.w);
            wp[4 * q + 2] = pk2(wB.x, wB.y);
            wp[4 * q + 3] = pk2(wB.z, wB.w);
        }
    }
    const float bias_t = __ldg(bias + tid);

    const int b0 = w, b1 = w + NWRK;         // 2 batches per worker

    for (int c = 0; c < T_ / CHUNK; c++) {
        const unsigned need = (unsigned)((c + 1) * CHUNK);
#pragma unroll 1
        for (int i = 0; i < 2; i++) {
            const int b = i ? b1 : b0;
            if (b >= B_) continue;
            if (tid == 0) {
                while (ld_acq(&g_flag0[b]) < need) npause();
            }
            __syncthreads();

            const size_t arow = (size_t)b * T_ + (size_t)c * CHUNK;

            for (int idx = tid; idx < 2048; idx += 384) {
                const int m = idx >> 5, c4 = idx & 31;
                cp_async16(sA_u32 + (uint32_t)(m * APAD + c4 * 4) * 4,
                           g_y0 + (arow + m) * H_ + c4 * 4);
            }
            cp_commit(); cp_wait0();
            __syncthreads();

            float* dst = g_gi1 + arow * G_ + tid;
#pragma unroll 1
            for (int m = 0; m < CHUNK; m++) {
                const ulonglong2* h2 = (const ulonglong2*)(sA + m * APAD);
                u64t a0 = 0ull, a1 = 0ull, a2 = 0ull, a3 = 0ull;
#pragma unroll
                for (int q = 0; q < 16; q++) {
                    ulonglong2 p0 = h2[2 * q];
                    ulonglong2 p1 = h2[2 * q + 1];
                    a0 = fma2(wp[4 * q + 0], p0.x, a0);
                    a1 = fma2(wp[4 * q + 1], p0.y, a1);
                    a2 = fma2(wp[4 * q + 2], p1.x, a2);
                    a3 = fma2(wp[4 * q + 3], p1.y, a3);
                }
                float2 sf = upk2(add2(add2(a0, a1), add2(a2, a3)));
                dst[(size_t)m * G_] = sf.x + sf.y + bias_t;
            }

            __threadfence();
            __syncthreads();
            if (tid == 0) st_rel(&g_flag1[b], need);
        }
    }
}

// ============================================================================
// Dual-batch scan role: one CTA advances TWO batches per iteration (shared
// layer weights in registers; matvec B issued right after matvec A so B's
// work fills A's stall slots). No FC here — FC runs in dedicated CTAs.
// gi via per-batch 8-deep cp.async rings (one commit group covers both).
// ============================================================================
__device__ __forceinline__ void scan_role2(
    int bA, int bB,
    const float* __restrict__ Whh, const float* __restrict__ bhh,
    const float* __restrict__ gi_base,
    float* __restrict__ ybuf,
    unsigned* pub, const unsigned* gateA, const unsigned* gateB,
    float* __restrict__ h_final,
    float* __restrict__ pool)
{
    float* sgiA = pool;                        // [GDEPTH][G_]
    float* sgiB = pool + GDEPTH * G_;
    float* shA0 = pool + 2 * GDEPTH * G_;      // h ping-pong A
    float* shA1 = shA0 + H_;
    float* shB0 = shA1 + H_;                   // h ping-pong B
    float* shB1 = shB0 + H_;
    float* s_rA = shB1 + H_;
    float* s_zA = s_rA + H_;
    float* s_rB = s_zA + H_;
    float* s_zB = s_rB + H_;

    const int r = threadIdx.x;   // gate row (r:0-127, z:128-255, n:256-383)

    u64t wp[64];
    {
        const float4* wr = (const float4*)(Whh + (size_t)r * H_);
#pragma unroll
        for (int q = 0; q < 16; q++) {
            float4 wA = __ldg(wr + 2 * q);
            float4 wB = __ldg(wr + 2 * q + 1);
            wp[4 * q + 0] = pk2(wA.x, wA.y);
            wp[4 * q + 1] = pk2(wA.z, wA.w);
            wp[4 * q + 2] = pk2(wB.x, wB.y);
            wp[4 * q + 3] = pk2(wB.z, wB.w);
        }
    }
    const float bias = __ldg(bhh + r);
    if (r < H_) { shA0[r] = 0.f; shB0[r] = 0.f; }

    const float* gipA = gi_base + (size_t)bA * T_ * G_ + r;
    const float* gipB = gi_base + (size_t)bB * T_ * G_ + r;
    const uint32_t sgA = smem_u32(sgiA + r);
    const uint32_t sgB = smem_u32(sgiB + r);

    unsigned knA = 0, knB = 0;
    if (gateA) {
        do { knA = ld_acq(gateA); if (knA < GDEPTH) npause(); } while (knA < GDEPTH);
        do { knB = ld_acq(gateB); if (knB < GDEPTH) npause(); } while (knB < GDEPTH);
    }
#pragma unroll
    for (int d = 0; d < GDEPTH; d++) {
        cp_async4(sgA + (uint32_t)d * (G_ * 4), gipA + (size_t)d * G_);
        cp_async4(sgB + (uint32_t)d * (G_ * 4), gipB + (size_t)d * G_);
        cp_commit();
    }
    __syncthreads();

    float* hcA = shA0; float* hnA = shA1;
    float* hcB = shB0; float* hnB = shB1;
    float* ybA = ybuf + (size_t)bA * T_ * H_ + (r - 256);      // n-threads only
    float* ybB = ybuf + (size_t)bB * T_ * H_ + (r - 256);

    float h_myA = 0.f, h_myB = 0.f;

    for (int t = 0; t < T_; t++) {
        const int slot = t & (GDEPTH - 1);

        cp_wait7();                                            // stage t landed
        const float giA = sgiA[slot * G_ + r];
        const float giB = sgiB[slot * G_ + r];

        // deferred y stores for step t-1 (under the matvec)
        if (r >= 256 && t > 0) {
            ybA[(size_t)(t - 1) * H_] = h_myA;
            ybB[(size_t)(t - 1) * H_] = h_myB;
        }

        // refill both slots for step t+GDEPTH (single commit group)
        const int tp = (t + GDEPTH < T_) ? t + GDEPTH : T_ - 1;
        if (gateA) {
            if (knA < (unsigned)(tp + 1)) {
                do { knA = ld_acq(gateA); if (knA < (unsigned)(tp + 1)) npause(); }
                while (knA < (unsigned)(tp + 1));
            }
            if (knB < (unsigned)(tp + 1)) {
                do { knB = ld_acq(gateB); if (knB < (unsigned)(tp + 1)) npause(); }
                while (knB < (unsigned)(tp + 1));
            }
        }
        cp_async4(sgA + (uint32_t)slot * (G_ * 4), gipA + (size_t)tp * G_);
        cp_async4(sgB + (uint32_t)slot * (G_ * 4), gipB + (size_t)tp * G_);
        cp_commit();

        // ---- phase 1: matvec A then matvec B (independent; fills stalls) ---
        u64t a0 = 0ull, a1 = 0ull, a2 = 0ull, a3 = 0ull;
        {
            const ulonglong2* h2 = (const ulonglong2*)hcA;
#pragma unroll
            for (int q = 0; q < 16; q++) {
                ulonglong2 p0 = h2[2 * q];
                ulonglong2 p1 = h2[2 * q + 1];
                a0 = fma2(wp[4 * q + 0], p0.x, a0);
                a1 = fma2(wp[4 * q + 1], p0.y, a1);
                a2 = fma2(wp[4 * q + 2], p1.x, a2);
                a3 = fma2(wp[4 * q + 3], p1.y, a3);
            }
        }
        float2 sfA = upk2(add2(add2(a0, a1), add2(a2, a3)));
        const float ghA = sfA.x + sfA.y + bias;

        a0 = a1 = a2 = a3 = 0ull;
        {
            const ulonglong2* h2 = (const ulonglong2*)hcB;
#pragma unroll
            for (int q = 0; q < 16; q++) {
                ulonglong2 p0 = h2[2 * q];
                ulonglong2 p1 = h2[2 * q + 1];
                a0 = fma2(wp[4 * q + 0], p0.x, a0);
                a1 = fma2(wp[4 * q + 1], p0.y, a1);
                a2 = fma2(wp[4 * q + 2], p1.x, a2);
                a3 = fma2(wp[4 * q + 3], p1.y, a3);
            }
        }
        float2 sfB = upk2(add2(add2(a0, a1), add2(a2, a3)));
        const float ghB = sfB.x + sfB.y + bias;

        if (r < 128) {
            s_rA[r] = sigmf(giA + ghA);
            s_rB[r] = sigmf(giB + ghB);
        } else if (r < 256) {
            s_zA[r - 128] = sigmf(giA + ghA);
            s_zB[r - 128] = sigmf(giB + ghB);
        }
        __syncthreads();                                        // bar 1

        // ---- phase 2: n-threads update both h states ----------------------
        if (r >= 256) {
            const int j = r - 256;
            const float nvA = tanhfast(fmaf(s_rA[j], ghA, giA));
            h_myA = fmaf(s_zA[j], h_myA - nvA, nvA);            // (1-z)n + z h
            hnA[j] = h_myA;
            const float nvB = tanhfast(fmaf(s_rB[j], ghB, giB));
            h_myB = fmaf(s_zB[j], h_myB - nvB, nvB);
            hnB[j] = h_myB;
        }

        const bool pub_now = ((t & 15) == 0) && (t > 0);
        if (pub_now) __threadfence();
        __syncthreads();                                        // bar 2
        if (pub_now) {
            if (r == 0)      st_rel(&pub[bA], (unsigned)t);
            else if (r == 1) st_rel(&pub[bB], (unsigned)t);
        }

        float* tmp;
        tmp = hcA; hcA = hnA; hnA = tmp;
        tmp = hcB; hcB = hnB; hnB = tmp;
    }

    // tail: last y rows + final flag publish
    if (r >= 256) {
        ybA[(size_t)(T_ - 1) * H_] = h_myA;
        ybB[(size_t)(T_ - 1) * H_] = h_myB;
    }
    __threadfence();
    __syncthreads();
    if (r == 0)      st_rel(&pub[bA], (unsigned)T_);
    else if (r == 1) st_rel(&pub[bB], (unsigned)T_);

    if (r >= 256) {
        h_final[(size_t)bA * H_ + (r - 256)] = h_myA;
        h_final[(size_t)bB * H_ + (r - 256)] = h_myB;
    }
}

// ============================================================================
// FC role: out[b,t,:] = y1[b,t,:] @ fcw^T + fcb, gated on g_flag2.
// 32-row half-chunks staged via cp.async; fcw cached in SMEM (pad 130).
// Warp = one row (broadcast y1), lane = out column. Coalesced stores.
// ============================================================================
__device__ __forceinline__ void fc_role(
    int f, const float* __restrict__ fcw, const float* __restrict__ fcb,
    float* __restrict__ out, float* __restrict__ pool)
{
    float* sy = pool;                        // 32 x APAD
    float* sw = pool + 32 * APAD;            // 32 x FCPAD
    const int tid = threadIdx.x;
    const int o = tid & 31, rb = tid >> 5;   // out col, warp id 0..11
    const uint32_t sy_u32 = smem_u32(sy);

    for (int i = tid; i < OUT_ * H_; i += 384) {
        const int oo = i >> 7, k = i & 127;
        sw[oo * FCPAD + k] = __ldg(fcw + i);
    }
    const float bo = __ldg(fcb + o);
    __syncthreads();

    int bs[3]; int nb = 0;
    for (int i = 0; i < 3; i++) {
        int bb = f + i * NFC;
        if (bb < B_) bs[nb++] = bb;
    }

    for (int c = 0; c < T_ / CHUNK; c++) {
        const unsigned need = (unsigned)((c + 1) * CHUNK);
        for (int i = 0; i < nb; i++) {
            const int b = bs[i];
            if (tid == 0) {
                while (ld_acq(&g_flag2[b]) < need) npause();
            }
#pragma unroll 1
            for (int half = 0; half < 2; half++) {
                const size_t row0 = (size_t)b * T_ + (size_t)c * CHUNK + half * 32;
                __syncthreads();             // flag visible + prior sy readers done

                for (int idx = tid; idx < 1024; idx += 384) {
                    const int m = idx >> 5, c4 = idx & 31;
                    cp_async16(sy_u32 + (uint32_t)(m * APAD + c4 * 4) * 4,
                               g_y1 + (row0 + m) * H_ + c4 * 4);
                }
                cp_commit(); cp_wait0();
                __syncthreads();

#pragma unroll 1
                for (int k3 = 0; k3 < 3; k3++) {
                    const int row = rb + 12 * k3;
                    if (row < 32) {
                        const u64t* wv = (const u64t*)(sw + o * FCPAD);
                        const u64t* yv = (const u64t*)(sy + row * APAD);
                        u64t f0 = 0ull, f1 = 0ull;
#pragma unroll
                        for (int q = 0; q < 32; q++) {
                            f0 = fma2(wv[2 * q],     yv[2 * q],     f0);
                            f1 = fma2(wv[2 * q + 1], yv[2 * q + 1], f1);
                        }
                        float2 s = upk2(add2(f0, f1));
                        out[(row0 + row) * OUT_ + o] = s.x + s.y + bo;
                    }
                }
            }
        }
    }
}

// ============================================================================
// Fused persistent kernel: 120 CTAs (GB300 152 SMs; all wave-1 resident).
//   CTA 0..31    : layer-0 dual scan (batches 2i, 2i+1) -> y0, flag0
//   CTA 32..63   : gi1 workers (batches w, w+32) -> gi1, flag1
//   CTA 64..95   : layer-1 dual scan (gated flag1) -> y1, flag2
//   CTA 96..119  : FC head (gated flag2) -> out
// ============================================================================
__global__ void __launch_bounds__(384, 1) k_fused(
    const float* __restrict__ Whh0, const float* __restrict__ bhh0,
    const float* __restrict__ Whh1, const float* __restrict__ bhh1,
    const float* __restrict__ Wih1, const float* __restrict__ bih1,
    const float* __restrict__ fcw,  const float* __restrict__ fcb,
    float* __restrict__ out, float* __restrict__ hout)
{
    __shared__ __align__(16) float pool[POOLF];

    const int bid = blockIdx.x;

    if (bid < NSC) {
        scan_role2(2 * bid, 2 * bid + 1, Whh0, bhh0, g_gi, g_y0,
                   g_flag0, nullptr, nullptr, hout, pool);
    } else if (bid < NSC + NWRK) {
        worker_role(bid - NSC, Wih1, bih1, pool);
    } else if (bid < NSC + NWRK + NSC) {
        const int i = bid - (NSC + NWRK);
        scan_role2(2 * i, 2 * i + 1, Whh1, bhh1, g_gi1, g_y1,
                   g_flag2, &g_flag1[2 * i], &g_flag1[2 * i + 1],
                   hout + (size_t)B_ * H_, pool);
    } else {
        fc_role(bid - (NSC + NWRK + NSC), fcw, fcb, out, pool);
    }
}

// ============================================================================
extern "C" void kernel_launch(void* const* d_in, const int* in_sizes, int n_in,
                              void* d_out, int out_size) {
    const float* x    = (const float*)d_in[0];
    const float* Wih0 = (const float*)d_in[1];
    const float* Whh0 = (const float*)d_in[2];
    const float* bih0 = (const float*)d_in[3];
    const float* bhh0 = (const float*)d_in[4];
    const float* Wih1 = (const float*)d_in[5];
    const float* Whh1 = (const float*)d_in[6];
    const float* bih1 = (const float*)d_in[7];
    const float* bhh1 = (const float*)d_in[8];
    const float* fcw  = (const float*)d_in[9];
    const float* fcb  = (const float*)d_in[10];

    float* out  = (float*)d_out;                       // [B,T,OUT]
    float* hout = out + (size_t)B_ * T_ * OUT_;        // [2,B,H] stacked after out

    // K1: layer-0 input projection + flag reset (graph-ordered before fused)
    k1_gi0<<<BT_ / K1ROWS, 384>>>(x, Wih0, bih0);
    // Fused pipeline: L0 dual scans || gi1 workers || L1 dual scans || FC
    k_fused<<<NSC + NWRK + NSC + NFC, 384>>>(Whh0, bhh0, Whh1, bhh1,
                                             Wih1, bih1, fcw, fcb, out, hout);
}